// round 1
// baseline (speedup 1.0000x reference)
#include <cuda_runtime.h>
#include <cstdint>
#include <cstddef>

#define BATCH 4
#define SEQ   1024
#define EMB   1024
#define NH    16
#define HD    64
#define BH    (BATCH * NH)      // 64
#define MROWS (BATCH * SEQ)     // 4096

// ---- scratch (device globals: allocation-free per harness rules) ----
__device__ float g_q[(size_t)BH * SEQ * HD];          // [B,H,S,D] 16 MB
__device__ float g_k[(size_t)BH * SEQ * HD];          // 16 MB
__device__ float g_v[(size_t)BH * SEQ * HD];          // 16 MB
__device__ float g_p[(size_t)BH * SEQ * SEQ];         // [BH,S,S] 256 MB
__device__ float g_o[(size_t)MROWS * EMB];            // [B,S,H*D] 16 MB

// ---- tf32 helpers ----
__device__ __forceinline__ uint32_t f2tf(float f) {
    uint32_t u;
    asm("cvt.rna.tf32.f32 %0, %1;" : "=r"(u) : "f"(f));
    return u;
}

__device__ __forceinline__ void mma8(float* c, const uint32_t* a, const uint32_t* b) {
    asm volatile(
        "mma.sync.aligned.m16n8k8.row.col.f32.tf32.tf32.f32 "
        "{%0,%1,%2,%3}, {%4,%5,%6,%7}, {%8,%9}, {%0,%1,%2,%3};\n"
        : "+f"(c[0]), "+f"(c[1]), "+f"(c[2]), "+f"(c[3])
        : "r"(a[0]), "r"(a[1]), "r"(a[2]), "r"(a[3]),
          "r"(b[0]), "r"(b[1]));
}

// ---- generic tf32 GEMM core: C[M,N] = A[M,K] * op(B) ----
// TRANSB=true : B is [N,K] row-major (weight layout, y = x W^T)
// TRANSB=false: B is [K,N] row-major
// Requires: BK==16, 256 threads, all tile dims divide shapes exactly.
template<int BM, int BN, int BK, int WM, int WN, bool TRANSB, int MT, int NT>
__device__ __forceinline__ void gemm_core(
    const float* __restrict__ A, int lda,
    const float* __restrict__ B, int ldb,
    int Kdim, int m0, int n0,
    float (&acc)[MT][NT][4])
{
    static_assert(BK == 16, "BK must be 16");
    static_assert(MT == WM / 16 && NT == WN / 8, "frag counts");
    __shared__ uint32_t As[BK][BM + 8];   // [k][m], stride BM+8 -> conflict-free frag loads
    __shared__ uint32_t Bs[BK][BN + 8];   // [k][n]

    const int tid  = threadIdx.x;
    const int lane = tid & 31;
    const int warp = tid >> 5;
    const int g  = lane >> 2;   // groupID
    const int tg = lane & 3;    // threadID_in_group
    constexpr int WARPS_N = BN / WN;
    const int wm = (warp / WARPS_N) * WM;
    const int wn = (warp % WARPS_N) * WN;

    for (int k0 = 0; k0 < Kdim; k0 += BK) {
        // --- stage A tile: BM x BK, gmem row-major, smem k-major ---
        #pragma unroll
        for (int i = 0; i < (BM * BK / 4) / 256; ++i) {
            int idx = tid + i * 256;
            int row = idx >> 2;               // BK/4 == 4
            int kq  = (idx & 3) << 2;
            float4 v = *reinterpret_cast<const float4*>(
                A + (size_t)(m0 + row) * lda + k0 + kq);
            As[kq + 0][row] = f2tf(v.x);
            As[kq + 1][row] = f2tf(v.y);
            As[kq + 2][row] = f2tf(v.z);
            As[kq + 3][row] = f2tf(v.w);
        }
        // --- stage B tile ---
        if (TRANSB) {
            #pragma unroll
            for (int i = 0; i < (BN * BK / 4) / 256; ++i) {
                int idx = tid + i * 256;
                int row = idx >> 2;
                int kq  = (idx & 3) << 2;
                float4 v = *reinterpret_cast<const float4*>(
                    B + (size_t)(n0 + row) * ldb + k0 + kq);
                Bs[kq + 0][row] = f2tf(v.x);
                Bs[kq + 1][row] = f2tf(v.y);
                Bs[kq + 2][row] = f2tf(v.z);
                Bs[kq + 3][row] = f2tf(v.w);
            }
        } else {
            #pragma unroll
            for (int i = 0; i < (BK * BN / 4) / 256; ++i) {
                int idx = tid + i * 256;
                int kr = idx / (BN / 4);
                int nq = (idx % (BN / 4)) << 2;
                float4 v = *reinterpret_cast<const float4*>(
                    B + (size_t)(k0 + kr) * ldb + n0 + nq);
                uint32_t* dst = &Bs[kr][nq];
                dst[0] = f2tf(v.x);
                dst[1] = f2tf(v.y);
                dst[2] = f2tf(v.z);
                dst[3] = f2tf(v.w);
            }
        }
        __syncthreads();

        // --- compute: BK/8 k-steps of m16n8k8 ---
        #pragma unroll
        for (int ks = 0; ks < BK / 8; ++ks) {
            uint32_t af[MT][4];
            uint32_t bf[NT][2];
            #pragma unroll
            for (int mt = 0; mt < MT; ++mt) {
                int r = wm + mt * 16 + g;
                af[mt][0] = As[ks * 8 + tg    ][r];
                af[mt][1] = As[ks * 8 + tg    ][r + 8];
                af[mt][2] = As[ks * 8 + tg + 4][r];
                af[mt][3] = As[ks * 8 + tg + 4][r + 8];
            }
            #pragma unroll
            for (int nt = 0; nt < NT; ++nt) {
                int c = wn + nt * 8 + g;
                bf[nt][0] = Bs[ks * 8 + tg    ][c];
                bf[nt][1] = Bs[ks * 8 + tg + 4][c];
            }
            #pragma unroll
            for (int mt = 0; mt < MT; ++mt)
                #pragma unroll
                for (int nt = 0; nt < NT; ++nt)
                    mma8(acc[mt][nt], af[mt], bf[nt]);
        }
        __syncthreads();
    }
}

// epilogue helper: store into [B,H,S,D] with bias over flattened (h,d)
__device__ __forceinline__ void st_bhsd(float* __restrict__ out,
                                        const float* __restrict__ bias,
                                        int r, int c, float v) {
    int b = r >> 10, s = r & 1023;
    int h = c >> 6,  d = c & 63;
    out[(((size_t)b * NH + h) * SEQ + s) * HD + d] = v + bias[c];
}

// ---- kernel 1: fused QKV projection (grid.z selects q/k/v) ----
__global__ void __launch_bounds__(256) qkv_kernel(
    const float* __restrict__ x,
    const float* __restrict__ Wq, const float* __restrict__ bq,
    const float* __restrict__ Wk, const float* __restrict__ bk,
    const float* __restrict__ Wv, const float* __restrict__ bv)
{
    constexpr int BM = 128, BN = 128, BK = 16, WM = 64, WN = 32;
    constexpr int MT = WM / 16, NT = WN / 8;
    const int z = blockIdx.z;
    const float* W    = (z == 0) ? Wq : ((z == 1) ? Wk : Wv);
    const float* bias = (z == 0) ? bq : ((z == 1) ? bk : bv);
    float* out        = (z == 0) ? g_q : ((z == 1) ? g_k : g_v);

    float acc[MT][NT][4] = {};
    const int m0 = blockIdx.x * BM, n0 = blockIdx.y * BN;
    gemm_core<BM, BN, BK, WM, WN, true, MT, NT>(x, EMB, W, EMB, EMB, m0, n0, acc);

    const int lane = threadIdx.x & 31, warp = threadIdx.x >> 5;
    const int g = lane >> 2, tg = lane & 3;
    const int wm = (warp / (BN / WN)) * WM, wn = (warp % (BN / WN)) * WN;
    #pragma unroll
    for (int mt = 0; mt < MT; ++mt)
        #pragma unroll
        for (int nt = 0; nt < NT; ++nt) {
            int r = m0 + wm + mt * 16 + g;
            int c = n0 + wn + nt * 8 + 2 * tg;
            st_bhsd(out, bias, r,     c,     acc[mt][nt][0]);
            st_bhsd(out, bias, r,     c + 1, acc[mt][nt][1]);
            st_bhsd(out, bias, r + 8, c,     acc[mt][nt][2]);
            st_bhsd(out, bias, r + 8, c + 1, acc[mt][nt][3]);
        }
}

// ---- kernel 2: scores = Q K^T * (1/8), per (b,h) ----
__global__ void __launch_bounds__(256) scores_kernel()
{
    constexpr int BM = 128, BN = 128, BK = 16, WM = 64, WN = 32;
    constexpr int MT = WM / 16, NT = WN / 8;
    const int z = blockIdx.z;   // bh
    const float* Q  = g_q + (size_t)z * SEQ * HD;
    const float* Kp = g_k + (size_t)z * SEQ * HD;
    float* out = g_p + (size_t)z * SEQ * SEQ;

    float acc[MT][NT][4] = {};
    const int m0 = blockIdx.x * BM, n0 = blockIdx.y * BN;
    gemm_core<BM, BN, BK, WM, WN, true, MT, NT>(Q, HD, Kp, HD, HD, m0, n0, acc);

    const int lane = threadIdx.x & 31, warp = threadIdx.x >> 5;
    const int g = lane >> 2, tg = lane & 3;
    const int wm = (warp / (BN / WN)) * WM, wn = (warp % (BN / WN)) * WN;
    #pragma unroll
    for (int mt = 0; mt < MT; ++mt)
        #pragma unroll
        for (int nt = 0; nt < NT; ++nt) {
            int r = m0 + wm + mt * 16 + g;
            int c = n0 + wn + nt * 8 + 2 * tg;
            out[(size_t)r * SEQ + c]           = acc[mt][nt][0] * 0.125f;
            out[(size_t)r * SEQ + c + 1]       = acc[mt][nt][1] * 0.125f;
            out[(size_t)(r + 8) * SEQ + c]     = acc[mt][nt][2] * 0.125f;
            out[(size_t)(r + 8) * SEQ + c + 1] = acc[mt][nt][3] * 0.125f;
        }
}

// ---- kernel 3: row softmax over last dim (len 1024), in place on g_p ----
__global__ void __launch_bounds__(256) softmax_kernel()
{
    const size_t row = blockIdx.x;
    float4* p4 = reinterpret_cast<float4*>(g_p + row * SEQ);
    const int tid = threadIdx.x;
    float4 v = p4[tid];

    float m = fmaxf(fmaxf(v.x, v.y), fmaxf(v.z, v.w));
    #pragma unroll
    for (int o = 16; o > 0; o >>= 1)
        m = fmaxf(m, __shfl_xor_sync(0xffffffffu, m, o));

    __shared__ float rbuf[8];
    const int warp = tid >> 5, lane = tid & 31;
    if (lane == 0) rbuf[warp] = m;
    __syncthreads();
    float gm = rbuf[0];
    #pragma unroll
    for (int i = 1; i < 8; ++i) gm = fmaxf(gm, rbuf[i]);

    float4 e;
    e.x = __expf(v.x - gm); e.y = __expf(v.y - gm);
    e.z = __expf(v.z - gm); e.w = __expf(v.w - gm);
    float s = e.x + e.y + e.z + e.w;
    #pragma unroll
    for (int o = 16; o > 0; o >>= 1)
        s += __shfl_xor_sync(0xffffffffu, s, o);

    __syncthreads();                 // rbuf reads (max) complete before reuse
    if (lane == 0) rbuf[warp] = s;
    __syncthreads();
    float gs = 0.f;
    #pragma unroll
    for (int i = 0; i < 8; ++i) gs += rbuf[i];

    const float inv = 1.0f / gs;
    e.x *= inv; e.y *= inv; e.z *= inv; e.w *= inv;
    p4[tid] = e;
}

// ---- kernel 4: O = P V, per (b,h); output concat layout [B,S,H*D] ----
__global__ void __launch_bounds__(256) pv_kernel()
{
    constexpr int BM = 128, BN = 64, BK = 16, WM = 32, WN = 32;
    constexpr int MT = WM / 16, NT = WN / 8;
    const int z = blockIdx.z;   // bh
    const float* P = g_p + (size_t)z * SEQ * SEQ;
    const float* V = g_v + (size_t)z * SEQ * HD;

    float acc[MT][NT][4] = {};
    const int m0 = blockIdx.x * BM, n0 = 0;
    gemm_core<BM, BN, BK, WM, WN, false, MT, NT>(P, SEQ, V, HD, SEQ, m0, n0, acc);

    const int b = z >> 4, h = z & 15;
    const int lane = threadIdx.x & 31, warp = threadIdx.x >> 5;
    const int g = lane >> 2, tg = lane & 3;
    const int wm = (warp / (BN / WN)) * WM, wn = (warp % (BN / WN)) * WN;
    #pragma unroll
    for (int mt = 0; mt < MT; ++mt)
        #pragma unroll
        for (int nt = 0; nt < NT; ++nt) {
            int s0 = m0 + wm + mt * 16 + g;
            int d0 = wn + nt * 8 + 2 * tg;
            size_t base0 = ((size_t)(b * SEQ + s0)) * EMB + h * HD;
            size_t base1 = ((size_t)(b * SEQ + s0 + 8)) * EMB + h * HD;
            g_o[base0 + d0]     = acc[mt][nt][0];
            g_o[base0 + d0 + 1] = acc[mt][nt][1];
            g_o[base1 + d0]     = acc[mt][nt][2];
            g_o[base1 + d0 + 1] = acc[mt][nt][3];
        }
}

// ---- kernel 5: out = concat @ Wo^T + bo ----
__global__ void __launch_bounds__(256) oproj_kernel(
    const float* __restrict__ Wo, const float* __restrict__ bo,
    float* __restrict__ out)
{
    constexpr int BM = 128, BN = 128, BK = 16, WM = 64, WN = 32;
    constexpr int MT = WM / 16, NT = WN / 8;
    float acc[MT][NT][4] = {};
    const int m0 = blockIdx.x * BM, n0 = blockIdx.y * BN;
    gemm_core<BM, BN, BK, WM, WN, true, MT, NT>(g_o, EMB, Wo, EMB, EMB, m0, n0, acc);

    const int lane = threadIdx.x & 31, warp = threadIdx.x >> 5;
    const int g = lane >> 2, tg = lane & 3;
    const int wm = (warp / (BN / WN)) * WM, wn = (warp % (BN / WN)) * WN;
    #pragma unroll
    for (int mt = 0; mt < MT; ++mt)
        #pragma unroll
        for (int nt = 0; nt < NT; ++nt) {
            int r = m0 + wm + mt * 16 + g;
            int c = n0 + wn + nt * 8 + 2 * tg;
            out[(size_t)r * EMB + c]           = acc[mt][nt][0] + bo[c];
            out[(size_t)r * EMB + c + 1]       = acc[mt][nt][1] + bo[c + 1];
            out[(size_t)(r + 8) * EMB + c]     = acc[mt][nt][2] + bo[c];
            out[(size_t)(r + 8) * EMB + c + 1] = acc[mt][nt][3] + bo[c + 1];
        }
}

extern "C" void kernel_launch(void* const* d_in, const int* in_sizes, int n_in,
                              void* d_out, int out_size)
{
    const float* x  = (const float*)d_in[0];
    const float* Wq = (const float*)d_in[1];
    const float* bq = (const float*)d_in[2];
    const float* Wk = (const float*)d_in[3];
    const float* bk = (const float*)d_in[4];
    const float* Wv = (const float*)d_in[5];
    const float* bv = (const float*)d_in[6];
    const float* Wo = (const float*)d_in[7];
    const float* bo = (const float*)d_in[8];
    float* out = (float*)d_out;

    qkv_kernel<<<dim3(MROWS / 128, EMB / 128, 3), 256>>>(x, Wq, bq, Wk, bk, Wv, bv);
    scores_kernel<<<dim3(SEQ / 128, SEQ / 128, BH), 256>>>();
    softmax_kernel<<<dim3(BH * SEQ), 256>>>();
    pv_kernel<<<dim3(SEQ / 128, 1, BH), 256>>>();
    oproj_kernel<<<dim3(MROWS / 128, EMB / 128, 1), 256>>>(Wo, bo, out);
}

// round 2
// speedup vs baseline: 1.1990x; 1.1990x over previous
#include <cuda_runtime.h>
#include <cstdint>
#include <cstddef>

#define BATCH 4
#define SEQ   1024
#define EMB   1024
#define NH    16
#define HD    64
#define BH    (BATCH * NH)      // 64
#define MROWS (BATCH * SEQ)     // 4096

// ---- scratch (device globals: allocation-free per harness rules) ----
__device__ float g_q[(size_t)BH * SEQ * HD];          // [B,H,S,D] 16 MB
__device__ float g_k[(size_t)BH * SEQ * HD];          // 16 MB
__device__ float g_v[(size_t)BH * SEQ * HD];          // 16 MB
__device__ float g_o[(size_t)MROWS * EMB];            // [B,S,H*D] 16 MB

// ---- tf32 helpers ----
__device__ __forceinline__ uint32_t f2tf(float f) {
    uint32_t u;
    asm("cvt.rna.tf32.f32 %0, %1;" : "=r"(u) : "f"(f));
    return u;
}

__device__ __forceinline__ void mma8(float* c, const uint32_t* a, const uint32_t* b) {
    asm volatile(
        "mma.sync.aligned.m16n8k8.row.col.f32.tf32.tf32.f32 "
        "{%0,%1,%2,%3}, {%4,%5,%6,%7}, {%8,%9}, {%0,%1,%2,%3};\n"
        : "+f"(c[0]), "+f"(c[1]), "+f"(c[2]), "+f"(c[3])
        : "r"(a[0]), "r"(a[1]), "r"(a[2]), "r"(a[3]),
          "r"(b[0]), "r"(b[1]));
}

// XOR swizzle: conflict-free-ish staging stores while keeping mma frag loads clean
__device__ __forceinline__ int fa_sw(int k, int r) {
    return r ^ (((k >> 2) & 7) << 2);
}

// ============================================================================
// generic tf32 GEMM core (validated round 1): C[M,N] = A[M,K] * op(B)
// ============================================================================
template<int BM, int BN, int BK, int WM, int WN, bool TRANSB, int MT, int NT>
__device__ __forceinline__ void gemm_core(
    const float* __restrict__ A, int lda,
    const float* __restrict__ B, int ldb,
    int Kdim, int m0, int n0,
    float (&acc)[MT][NT][4])
{
    static_assert(BK == 16, "BK must be 16");
    static_assert(MT == WM / 16 && NT == WN / 8, "frag counts");
    __shared__ uint32_t As[BK][BM + 8];
    __shared__ uint32_t Bs[BK][BN + 8];

    const int tid  = threadIdx.x;
    const int lane = tid & 31;
    const int warp = tid >> 5;
    const int g  = lane >> 2;
    const int tg = lane & 3;
    constexpr int WARPS_N = BN / WN;
    const int wm = (warp / WARPS_N) * WM;
    const int wn = (warp % WARPS_N) * WN;

    for (int k0 = 0; k0 < Kdim; k0 += BK) {
        #pragma unroll
        for (int i = 0; i < (BM * BK / 4) / 256; ++i) {
            int idx = tid + i * 256;
            int row = idx >> 2;
            int kq  = (idx & 3) << 2;
            float4 v = *reinterpret_cast<const float4*>(
                A + (size_t)(m0 + row) * lda + k0 + kq);
            As[kq + 0][row] = f2tf(v.x);
            As[kq + 1][row] = f2tf(v.y);
            As[kq + 2][row] = f2tf(v.z);
            As[kq + 3][row] = f2tf(v.w);
        }
        if (TRANSB) {
            #pragma unroll
            for (int i = 0; i < (BN * BK / 4) / 256; ++i) {
                int idx = tid + i * 256;
                int row = idx >> 2;
                int kq  = (idx & 3) << 2;
                float4 v = *reinterpret_cast<const float4*>(
                    B + (size_t)(n0 + row) * ldb + k0 + kq);
                Bs[kq + 0][row] = f2tf(v.x);
                Bs[kq + 1][row] = f2tf(v.y);
                Bs[kq + 2][row] = f2tf(v.z);
                Bs[kq + 3][row] = f2tf(v.w);
            }
        } else {
            #pragma unroll
            for (int i = 0; i < (BK * BN / 4) / 256; ++i) {
                int idx = tid + i * 256;
                int kr = idx / (BN / 4);
                int nq = (idx % (BN / 4)) << 2;
                float4 v = *reinterpret_cast<const float4*>(
                    B + (size_t)(k0 + kr) * ldb + n0 + nq);
                uint32_t* dst = &Bs[kr][nq];
                dst[0] = f2tf(v.x);
                dst[1] = f2tf(v.y);
                dst[2] = f2tf(v.z);
                dst[3] = f2tf(v.w);
            }
        }
        __syncthreads();

        #pragma unroll
        for (int ks = 0; ks < BK / 8; ++ks) {
            uint32_t af[MT][4];
            uint32_t bf[NT][2];
            #pragma unroll
            for (int mt = 0; mt < MT; ++mt) {
                int r = wm + mt * 16 + g;
                af[mt][0] = As[ks * 8 + tg    ][r];
                af[mt][1] = As[ks * 8 + tg    ][r + 8];
                af[mt][2] = As[ks * 8 + tg + 4][r];
                af[mt][3] = As[ks * 8 + tg + 4][r + 8];
            }
            #pragma unroll
            for (int nt = 0; nt < NT; ++nt) {
                int c = wn + nt * 8 + g;
                bf[nt][0] = Bs[ks * 8 + tg    ][c];
                bf[nt][1] = Bs[ks * 8 + tg + 4][c];
            }
            #pragma unroll
            for (int mt = 0; mt < MT; ++mt)
                #pragma unroll
                for (int nt = 0; nt < NT; ++nt)
                    mma8(acc[mt][nt], af[mt], bf[nt]);
        }
        __syncthreads();
    }
}

__device__ __forceinline__ void st_bhsd(float* __restrict__ out,
                                        const float* __restrict__ bias,
                                        int r, int c, float v) {
    int b = r >> 10, s = r & 1023;
    int h = c >> 6,  d = c & 63;
    out[(((size_t)b * NH + h) * SEQ + s) * HD + d] = v + bias[c];
}

// ---- kernel 1: fused QKV projection (grid.z selects q/k/v) ----
__global__ void __launch_bounds__(256) qkv_kernel(
    const float* __restrict__ x,
    const float* __restrict__ Wq, const float* __restrict__ bq,
    const float* __restrict__ Wk, const float* __restrict__ bk,
    const float* __restrict__ Wv, const float* __restrict__ bv)
{
    constexpr int BM = 128, BN = 128, BK = 16, WM = 64, WN = 32;
    constexpr int MT = WM / 16, NT = WN / 8;
    const int z = blockIdx.z;
    const float* W    = (z == 0) ? Wq : ((z == 1) ? Wk : Wv);
    const float* bias = (z == 0) ? bq : ((z == 1) ? bk : bv);
    float* out        = (z == 0) ? g_q : ((z == 1) ? g_k : g_v);

    float acc[MT][NT][4] = {};
    const int m0 = blockIdx.x * BM, n0 = blockIdx.y * BN;
    gemm_core<BM, BN, BK, WM, WN, true, MT, NT>(x, EMB, W, EMB, EMB, m0, n0, acc);

    const int lane = threadIdx.x & 31, warp = threadIdx.x >> 5;
    const int g = lane >> 2, tg = lane & 3;
    const int wm = (warp / (BN / WN)) * WM, wn = (warp % (BN / WN)) * WN;
    #pragma unroll
    for (int mt = 0; mt < MT; ++mt)
        #pragma unroll
        for (int nt = 0; nt < NT; ++nt) {
            int r = m0 + wm + mt * 16 + g;
            int c = n0 + wn + nt * 8 + 2 * tg;
            st_bhsd(out, bias, r,     c,     acc[mt][nt][0]);
            st_bhsd(out, bias, r,     c + 1, acc[mt][nt][1]);
            st_bhsd(out, bias, r + 8, c,     acc[mt][nt][2]);
            st_bhsd(out, bias, r + 8, c + 1, acc[mt][nt][3]);
        }
}

// ============================================================================
// kernel 2: fused flash attention (scores + softmax + PV) per (b,h)
// Q tile 128 rows, streaming 64-key K/V tiles, online softmax.
// ============================================================================
#define FA_BM 128
#define FA_BN 64
#define FA_QS_SZ (64 * 136)
#define FA_KS_SZ (64 * 72)
#define FA_VS_SZ (64 * 72)
#define FA_PS_SZ (64 * 136)
#define FA_SMEM_WORDS (FA_QS_SZ + FA_KS_SZ + FA_VS_SZ + FA_PS_SZ + 512)

__global__ void __launch_bounds__(256, 2) flash_kernel()
{
    extern __shared__ uint32_t sm[];
    uint32_t* Qs = sm;                      // [64 d][136]  (col = q-row, swizzled)
    uint32_t* Ks = Qs + FA_QS_SZ;           // [64 d][72]   (col = key,  swizzled)
    uint32_t* Vs = Ks + FA_KS_SZ;           // [64 k][72]   (col = d, natural)
    uint32_t* Ps = Vs + FA_VS_SZ;           // [64 k][136]  (col = q-row, swizzled)
    float* redA  = (float*)(Ps + FA_PS_SZ); // [2][128]
    float* redB  = redA + 256;              // [2][128]

    const int z  = blockIdx.z;              // bh
    const int m0 = blockIdx.x * FA_BM;
    const float* Q  = g_q + (size_t)z * SEQ * HD;
    const float* Kg = g_k + (size_t)z * SEQ * HD;
    const float* Vg = g_v + (size_t)z * SEQ * HD;

    const int tid  = threadIdx.x;
    const int lane = tid & 31, warp = tid >> 5;
    const int g = lane >> 2, tg = lane & 3;
    const int mw = warp >> 1, nw = warp & 1;
    const int wm = mw * 32;
    const int wn = nw * 32;

    // ---- stage Q tile once: [128 rows][64 d] -> Qs[d][row] ----
    #pragma unroll
    for (int i = 0; i < 8; ++i) {
        int idx = tid + i * 256;
        int r  = idx >> 4;
        int kq = (idx & 15) << 2;
        float4 v = *reinterpret_cast<const float4*>(Q + (size_t)(m0 + r) * HD + kq);
        int sr = fa_sw(kq, r);              // same swizzle for kq..kq+3
        Qs[(kq + 0) * 136 + sr] = f2tf(v.x);
        Qs[(kq + 1) * 136 + sr] = f2tf(v.y);
        Qs[(kq + 2) * 136 + sr] = f2tf(v.z);
        Qs[(kq + 3) * 136 + sr] = f2tf(v.w);
    }

    float acc_o[2][4][4] = {};
    float m_st[2][2] = {{-1e30f, -1e30f}, {-1e30f, -1e30f}};
    float l_st[2][2] = {};

    for (int n0 = 0; n0 < SEQ; n0 += FA_BN) {
        __syncthreads();   // previous iter's Ks/Vs/Ps reads complete

        // ---- stage K tile: [64 keys][64 d] -> Ks[d][key] (swizzled) ----
        #pragma unroll
        for (int i = 0; i < 4; ++i) {
            int idx = tid + i * 256;
            int n  = idx >> 4;
            int kq = (idx & 15) << 2;
            float4 v = *reinterpret_cast<const float4*>(Kg + (size_t)(n0 + n) * HD + kq);
            int sn = fa_sw(kq, n);
            Ks[(kq + 0) * 72 + sn] = f2tf(v.x);
            Ks[(kq + 1) * 72 + sn] = f2tf(v.y);
            Ks[(kq + 2) * 72 + sn] = f2tf(v.z);
            Ks[(kq + 3) * 72 + sn] = f2tf(v.w);
        }
        // ---- stage V tile: [64 keys][64 d] -> Vs[key][d] (natural) ----
        #pragma unroll
        for (int i = 0; i < 4; ++i) {
            int idx = tid + i * 256;
            int k  = idx >> 4;
            int dq = (idx & 15) << 2;
            float4 v = *reinterpret_cast<const float4*>(Vg + (size_t)(n0 + k) * HD + dq);
            uint32_t* dst = &Vs[k * 72 + dq];
            dst[0] = f2tf(v.x);
            dst[1] = f2tf(v.y);
            dst[2] = f2tf(v.z);
            dst[3] = f2tf(v.w);
        }
        __syncthreads();

        // ---- S = Q K^T (tile 128x64), warp covers [wm..wm+32) x [wn..wn+32) ----
        float acc_s[2][4][4] = {};
        #pragma unroll
        for (int ks = 0; ks < 8; ++ks) {
            uint32_t af[2][4];
            uint32_t bf[4][2];
            int k0 = ks * 8 + tg, k1 = k0 + 4;
            #pragma unroll
            for (int mt = 0; mt < 2; ++mt) {
                int r = wm + mt * 16 + g;
                af[mt][0] = Qs[k0 * 136 + fa_sw(k0, r)];
                af[mt][1] = Qs[k0 * 136 + fa_sw(k0, r + 8)];
                af[mt][2] = Qs[k1 * 136 + fa_sw(k1, r)];
                af[mt][3] = Qs[k1 * 136 + fa_sw(k1, r + 8)];
            }
            #pragma unroll
            for (int nt = 0; nt < 4; ++nt) {
                int c = wn + nt * 8 + g;
                bf[nt][0] = Ks[k0 * 72 + fa_sw(k0, c)];
                bf[nt][1] = Ks[k1 * 72 + fa_sw(k1, c)];
            }
            #pragma unroll
            for (int mt = 0; mt < 2; ++mt)
                #pragma unroll
                for (int nt = 0; nt < 4; ++nt)
                    mma8(acc_s[mt][nt], af[mt], bf[nt]);
        }
        // fold the 1/sqrt(D)=0.125 scale
        #pragma unroll
        for (int mt = 0; mt < 2; ++mt)
            #pragma unroll
            for (int nt = 0; nt < 4; ++nt)
                #pragma unroll
                for (int e = 0; e < 4; ++e)
                    acc_s[mt][nt][e] *= 0.125f;

        // ---- row max (intra-warp quad shuffle, then cross-N-warp via smem) ----
        float rmax[2][2];
        #pragma unroll
        for (int mt = 0; mt < 2; ++mt)
            #pragma unroll
            for (int h = 0; h < 2; ++h) {
                float m = -1e30f;
                #pragma unroll
                for (int nt = 0; nt < 4; ++nt)
                    m = fmaxf(m, fmaxf(acc_s[mt][nt][2 * h], acc_s[mt][nt][2 * h + 1]));
                m = fmaxf(m, __shfl_xor_sync(0xffffffffu, m, 1));
                m = fmaxf(m, __shfl_xor_sync(0xffffffffu, m, 2));
                rmax[mt][h] = m;
                if (tg == 0) redA[nw * 128 + wm + mt * 16 + g + 8 * h] = m;
            }
        __syncthreads();

        // ---- online softmax update + write P to SMEM ----
        float rsum[2][2];
        #pragma unroll
        for (int mt = 0; mt < 2; ++mt)
            #pragma unroll
            for (int h = 0; h < 2; ++h) {
                int row = wm + mt * 16 + g + 8 * h;
                float m = fmaxf(redA[row], redA[128 + row]);
                float mnew = fmaxf(m_st[mt][h], m);
                float scale = __expf(m_st[mt][h] - mnew);
                m_st[mt][h] = mnew;
                l_st[mt][h] *= scale;
                #pragma unroll
                for (int nt = 0; nt < 4; ++nt) {
                    acc_o[mt][nt][2 * h]     *= scale;
                    acc_o[mt][nt][2 * h + 1] *= scale;
                }
                float rs = 0.f;
                #pragma unroll
                for (int nt = 0; nt < 4; ++nt) {
                    int c = wn + nt * 8 + 2 * tg;
                    float p0 = __expf(acc_s[mt][nt][2 * h]     - mnew);
                    float p1 = __expf(acc_s[mt][nt][2 * h + 1] - mnew);
                    rs += p0 + p1;
                    int rr = wm + mt * 16 + g + 8 * h;
                    Ps[c * 136 + fa_sw(c, rr)]             = f2tf(p0);
                    Ps[(c + 1) * 136 + fa_sw(c + 1, rr)]   = f2tf(p1);
                }
                rs += __shfl_xor_sync(0xffffffffu, rs, 1);
                rs += __shfl_xor_sync(0xffffffffu, rs, 2);
                rsum[mt][h] = rs;
                if (tg == 0) redB[nw * 128 + row] = rs;
            }
        __syncthreads();   // P + redB visible

        #pragma unroll
        for (int mt = 0; mt < 2; ++mt)
            #pragma unroll
            for (int h = 0; h < 2; ++h) {
                int row = wm + mt * 16 + g + 8 * h;
                l_st[mt][h] += redB[row] + redB[128 + row];
            }

        // ---- O += P V (A = Ps[k][r], B = Vs[k][d]) ----
        #pragma unroll
        for (int ks = 0; ks < 8; ++ks) {
            uint32_t af[2][4];
            uint32_t bf[4][2];
            int k0 = ks * 8 + tg, k1 = k0 + 4;
            #pragma unroll
            for (int mt = 0; mt < 2; ++mt) {
                int r = wm + mt * 16 + g;
                af[mt][0] = Ps[k0 * 136 + fa_sw(k0, r)];
                af[mt][1] = Ps[k0 * 136 + fa_sw(k0, r + 8)];
                af[mt][2] = Ps[k1 * 136 + fa_sw(k1, r)];
                af[mt][3] = Ps[k1 * 136 + fa_sw(k1, r + 8)];
            }
            #pragma unroll
            for (int nt = 0; nt < 4; ++nt) {
                int d = wn + nt * 8 + g;
                bf[nt][0] = Vs[k0 * 72 + d];
                bf[nt][1] = Vs[k1 * 72 + d];
            }
            #pragma unroll
            for (int mt = 0; mt < 2; ++mt)
                #pragma unroll
                for (int nt = 0; nt < 4; ++nt)
                    mma8(acc_o[mt][nt], af[mt], bf[nt]);
        }
        (void)rmax; (void)rsum;
    }

    // ---- epilogue: O /= l, write concat layout [B,S,H*D] ----
    const int b = z >> 4, h = z & 15;
    #pragma unroll
    for (int mt = 0; mt < 2; ++mt) {
        float inv0 = 1.0f / l_st[mt][0];
        float inv1 = 1.0f / l_st[mt][1];
        #pragma unroll
        for (int nt = 0; nt < 4; ++nt) {
            int s0 = m0 + wm + mt * 16 + g;
            int d0 = wn + nt * 8 + 2 * tg;
            size_t base0 = ((size_t)(b * SEQ + s0)) * EMB + h * HD;
            size_t base1 = base0 + (size_t)8 * EMB;
            g_o[base0 + d0]     = acc_o[mt][nt][0] * inv0;
            g_o[base0 + d0 + 1] = acc_o[mt][nt][1] * inv0;
            g_o[base1 + d0]     = acc_o[mt][nt][2] * inv1;
            g_o[base1 + d0 + 1] = acc_o[mt][nt][3] * inv1;
        }
    }
}

// ---- kernel 3: out = concat @ Wo^T + bo ----
__global__ void __launch_bounds__(256) oproj_kernel(
    const float* __restrict__ Wo, const float* __restrict__ bo,
    float* __restrict__ out)
{
    constexpr int BM = 128, BN = 128, BK = 16, WM = 64, WN = 32;
    constexpr int MT = WM / 16, NT = WN / 8;
    float acc[MT][NT][4] = {};
    const int m0 = blockIdx.x * BM, n0 = blockIdx.y * BN;
    gemm_core<BM, BN, BK, WM, WN, true, MT, NT>(g_o, EMB, Wo, EMB, EMB, m0, n0, acc);

    const int lane = threadIdx.x & 31, warp = threadIdx.x >> 5;
    const int g = lane >> 2, tg = lane & 3;
    const int wm = (warp / (BN / WN)) * WM, wn = (warp % (BN / WN)) * WN;
    #pragma unroll
    for (int mt = 0; mt < MT; ++mt)
        #pragma unroll
        for (int nt = 0; nt < NT; ++nt) {
            int r = m0 + wm + mt * 16 + g;
            int c = n0 + wn + nt * 8 + 2 * tg;
            out[(size_t)r * EMB + c]           = acc[mt][nt][0] + bo[c];
            out[(size_t)r * EMB + c + 1]       = acc[mt][nt][1] + bo[c + 1];
            out[(size_t)(r + 8) * EMB + c]     = acc[mt][nt][2] + bo[c];
            out[(size_t)(r + 8) * EMB + c + 1] = acc[mt][nt][3] + bo[c + 1];
        }
}

extern "C" void kernel_launch(void* const* d_in, const int* in_sizes, int n_in,
                              void* d_out, int out_size)
{
    const float* x  = (const float*)d_in[0];
    const float* Wq = (const float*)d_in[1];
    const float* bq = (const float*)d_in[2];
    const float* Wk = (const float*)d_in[3];
    const float* bk = (const float*)d_in[4];
    const float* Wv = (const float*)d_in[5];
    const float* bv = (const float*)d_in[6];
    const float* Wo = (const float*)d_in[7];
    const float* bo = (const float*)d_in[8];
    float* out = (float*)d_out;

    const int fa_smem = FA_SMEM_WORDS * 4;   // 108544 B
    cudaFuncSetAttribute(flash_kernel,
                         cudaFuncAttributeMaxDynamicSharedMemorySize, fa_smem);

    qkv_kernel<<<dim3(MROWS / 128, EMB / 128, 3), 256>>>(x, Wq, bq, Wk, bk, Wv, bv);
    flash_kernel<<<dim3(SEQ / FA_BM, 1, BH), 256, fa_smem>>>();
    oproj_kernel<<<dim3(MROWS / 128, EMB / 128, 1), 256>>>(Wo, bo, out);
}

// round 3
// speedup vs baseline: 1.8326x; 1.5284x over previous
#include <cuda_runtime.h>
#include <cstdint>
#include <cstddef>

#define BATCH 4
#define SEQ   1024
#define EMB   1024
#define NH    16
#define HD    64
#define BH    (BATCH * NH)      // 64
#define MROWS (BATCH * SEQ)     // 4096

// ---- scratch (device globals: allocation-free per harness rules) ----
__device__ float g_q[(size_t)BH * SEQ * HD];          // [B,H,S,D] 16 MB
__device__ float g_k[(size_t)BH * SEQ * HD];          // 16 MB
__device__ float g_v[(size_t)BH * SEQ * HD];          // 16 MB
__device__ float g_o[(size_t)MROWS * EMB];            // [B,S,H*D] 16 MB

// ---- tf32 helpers ----
__device__ __forceinline__ uint32_t f2tf(float f) {
    uint32_t u;
    asm("cvt.rna.tf32.f32 %0, %1;" : "=r"(u) : "f"(f));
    return u;
}

__device__ __forceinline__ void mma8(float* c, const uint32_t* a, const uint32_t* b) {
    asm volatile(
        "mma.sync.aligned.m16n8k8.row.col.f32.tf32.tf32.f32 "
        "{%0,%1,%2,%3}, {%4,%5,%6,%7}, {%8,%9}, {%0,%1,%2,%3};\n"
        : "+f"(c[0]), "+f"(c[1]), "+f"(c[2]), "+f"(c[3])
        : "r"(a[0]), "r"(a[1]), "r"(a[2]), "r"(a[3]),
          "r"(b[0]), "r"(b[1]));
}

__device__ __forceinline__ void cp16(uint32_t dst, const void* src) {
    asm volatile("cp.async.cg.shared.global [%0], [%1], 16;\n"
                 :: "r"(dst), "l"(src));
}

// XOR swizzle for flash kernel smem
__device__ __forceinline__ int fa_sw(int k, int r) {
    return r ^ (((k >> 2) & 7) << 2);
}

// ============================================================================
// double-buffered cp.async tf32 GEMM core: C[M,N] = A[M,K] * B[N,K]^T
// Both operands row-major with K contiguous (x-by-weight layout).
// BK=32, fp32 staged raw, tf32 conversion at fragment load.
// 256 threads; 8 warps as (BM/WM) x (BN/WN).
// ============================================================================
#define GC_BM 128
#define GC_BN 128
#define GC_BK 32
#define GC_WM 64
#define GC_WN 32
#define GC_LDT (GC_BK + 4)                       // 36 words
#define GC_TILE (GC_BM * GC_LDT)                 // words per A stage (=B stage)
#define GC_SMEM_BYTES (4 * GC_TILE * 4 * 4 / 4)  // 2 bufs * 2 ops * TILE * 4B
// = 2*2*4608*4 = 73728 B

template<int MT, int NT>
__device__ __forceinline__ void gemm_core2(
    const float* __restrict__ A, int lda,
    const float* __restrict__ B, int ldb,
    int Kdim, int m0, int n0,
    float (&acc)[MT][NT][4])
{
    extern __shared__ float smem[];
    float* As = smem;                    // [2][BM][LDT]
    float* Bs = smem + 2 * GC_TILE;      // [2][BN][LDT]
    const uint32_t a_sb = (uint32_t)__cvta_generic_to_shared(As);
    const uint32_t b_sb = (uint32_t)__cvta_generic_to_shared(Bs);

    const int tid  = threadIdx.x;
    const int lane = tid & 31;
    const int warp = tid >> 5;
    const int g  = lane >> 2;
    const int tg = lane & 3;
    constexpr int WARPS_N = GC_BN / GC_WN;
    const int wm = (warp / WARPS_N) * GC_WM;
    const int wn = (warp % WARPS_N) * GC_WN;

    // stage one BK-slab of A and B into buffer `buf`
    auto stage = [&](int buf, int k0) {
        #pragma unroll
        for (int i = 0; i < (GC_BM * GC_BK / 4) / 256; ++i) {   // 4 iters
            int idx = tid + i * 256;
            int row = idx >> 3;           // 8 float4 per row (BK=32)
            int q   = (idx & 7) << 2;     // word offset within row
            cp16(a_sb + (uint32_t)((buf * GC_BM + row) * GC_LDT + q) * 4,
                 A + (size_t)(m0 + row) * lda + k0 + q);
            cp16(b_sb + (uint32_t)((buf * GC_BN + row) * GC_LDT + q) * 4,
                 B + (size_t)(n0 + row) * ldb + k0 + q);
        }
    };

    stage(0, 0);
    asm volatile("cp.async.commit_group;\n");

    int s = 0;
    for (int k0 = 0; k0 < Kdim; k0 += GC_BK, s ^= 1) {
        if (k0 + GC_BK < Kdim) stage(s ^ 1, k0 + GC_BK);
        asm volatile("cp.async.commit_group;\n");
        asm volatile("cp.async.wait_group 1;\n");
        __syncthreads();

        const float* Ab = As + s * GC_TILE;
        const float* Bb = Bs + s * GC_TILE;
        #pragma unroll
        for (int ks = 0; ks < GC_BK / 8; ++ks) {
            uint32_t af[MT][4];
            uint32_t bf[NT][2];
            int kk0 = ks * 8 + tg, kk1 = kk0 + 4;
            #pragma unroll
            for (int mt = 0; mt < MT; ++mt) {
                int r = wm + mt * 16 + g;
                af[mt][0] = f2tf(Ab[r * GC_LDT + kk0]);
                af[mt][1] = f2tf(Ab[(r + 8) * GC_LDT + kk0]);
                af[mt][2] = f2tf(Ab[r * GC_LDT + kk1]);
                af[mt][3] = f2tf(Ab[(r + 8) * GC_LDT + kk1]);
            }
            #pragma unroll
            for (int nt = 0; nt < NT; ++nt) {
                int c = wn + nt * 8 + g;
                bf[nt][0] = f2tf(Bb[c * GC_LDT + kk0]);
                bf[nt][1] = f2tf(Bb[c * GC_LDT + kk1]);
            }
            #pragma unroll
            for (int mt = 0; mt < MT; ++mt)
                #pragma unroll
                for (int nt = 0; nt < NT; ++nt)
                    mma8(acc[mt][nt], af[mt], bf[nt]);
        }
        __syncthreads();
    }
}

__device__ __forceinline__ void st_bhsd(float* __restrict__ out,
                                        const float* __restrict__ bias,
                                        int r, int c, float v) {
    int b = r >> 10, s = r & 1023;
    int h = c >> 6,  d = c & 63;
    out[(((size_t)b * NH + h) * SEQ + s) * HD + d] = v + bias[c];
}

// ---- kernel 1: fused QKV projection (grid.z selects q/k/v) ----
__global__ void __launch_bounds__(256, 2) qkv_kernel(
    const float* __restrict__ x,
    const float* __restrict__ Wq, const float* __restrict__ bq,
    const float* __restrict__ Wk, const float* __restrict__ bk,
    const float* __restrict__ Wv, const float* __restrict__ bv)
{
    constexpr int MT = GC_WM / 16, NT = GC_WN / 8;
    const int z = blockIdx.z;
    const float* W    = (z == 0) ? Wq : ((z == 1) ? Wk : Wv);
    const float* bias = (z == 0) ? bq : ((z == 1) ? bk : bv);
    float* out        = (z == 0) ? g_q : ((z == 1) ? g_k : g_v);

    float acc[MT][NT][4] = {};
    const int m0 = blockIdx.x * GC_BM, n0 = blockIdx.y * GC_BN;
    gemm_core2<MT, NT>(x, EMB, W, EMB, EMB, m0, n0, acc);

    const int lane = threadIdx.x & 31, warp = threadIdx.x >> 5;
    const int g = lane >> 2, tg = lane & 3;
    const int wm = (warp / (GC_BN / GC_WN)) * GC_WM;
    const int wn = (warp % (GC_BN / GC_WN)) * GC_WN;
    #pragma unroll
    for (int mt = 0; mt < MT; ++mt)
        #pragma unroll
        for (int nt = 0; nt < NT; ++nt) {
            int r = m0 + wm + mt * 16 + g;
            int c = n0 + wn + nt * 8 + 2 * tg;
            st_bhsd(out, bias, r,     c,     acc[mt][nt][0]);
            st_bhsd(out, bias, r,     c + 1, acc[mt][nt][1]);
            st_bhsd(out, bias, r + 8, c,     acc[mt][nt][2]);
            st_bhsd(out, bias, r + 8, c + 1, acc[mt][nt][3]);
        }
}

// ---- kernel 3: out = concat @ Wo^T + bo ----
__global__ void __launch_bounds__(256, 2) oproj_kernel(
    const float* __restrict__ Wo, const float* __restrict__ bo,
    float* __restrict__ out)
{
    constexpr int MT = GC_WM / 16, NT = GC_WN / 8;
    float acc[MT][NT][4] = {};
    const int m0 = blockIdx.x * GC_BM, n0 = blockIdx.y * GC_BN;
    gemm_core2<MT, NT>(g_o, EMB, Wo, EMB, EMB, m0, n0, acc);

    const int lane = threadIdx.x & 31, warp = threadIdx.x >> 5;
    const int g = lane >> 2, tg = lane & 3;
    const int wm = (warp / (GC_BN / GC_WN)) * GC_WM;
    const int wn = (warp % (GC_BN / GC_WN)) * GC_WN;
    #pragma unroll
    for (int mt = 0; mt < MT; ++mt)
        #pragma unroll
        for (int nt = 0; nt < NT; ++nt) {
            int r = m0 + wm + mt * 16 + g;
            int c = n0 + wn + nt * 8 + 2 * tg;
            out[(size_t)r * EMB + c]           = acc[mt][nt][0] + bo[c];
            out[(size_t)r * EMB + c + 1]       = acc[mt][nt][1] + bo[c + 1];
            out[(size_t)(r + 8) * EMB + c]     = acc[mt][nt][2] + bo[c];
            out[(size_t)(r + 8) * EMB + c + 1] = acc[mt][nt][3] + bo[c + 1];
        }
}

// ============================================================================
// kernel 2: fused flash attention (unchanged from round 2)
// ============================================================================
#define FA_BM 128
#define FA_BN 64
#define FA_QS_SZ (64 * 136)
#define FA_KS_SZ (64 * 72)
#define FA_VS_SZ (64 * 72)
#define FA_PS_SZ (64 * 136)
#define FA_SMEM_WORDS (FA_QS_SZ + FA_KS_SZ + FA_VS_SZ + FA_PS_SZ + 512)

__global__ void __launch_bounds__(256, 2) flash_kernel()
{
    extern __shared__ uint32_t sm[];
    uint32_t* Qs = sm;
    uint32_t* Ks = Qs + FA_QS_SZ;
    uint32_t* Vs = Ks + FA_KS_SZ;
    uint32_t* Ps = Vs + FA_VS_SZ;
    float* redA  = (float*)(Ps + FA_PS_SZ);
    float* redB  = redA + 256;

    const int z  = blockIdx.z;
    const int m0 = blockIdx.x * FA_BM;
    const float* Q  = g_q + (size_t)z * SEQ * HD;
    const float* Kg = g_k + (size_t)z * SEQ * HD;
    const float* Vg = g_v + (size_t)z * SEQ * HD;

    const int tid  = threadIdx.x;
    const int lane = tid & 31, warp = tid >> 5;
    const int g = lane >> 2, tg = lane & 3;
    const int mw = warp >> 1, nw = warp & 1;
    const int wm = mw * 32;
    const int wn = nw * 32;

    #pragma unroll
    for (int i = 0; i < 8; ++i) {
        int idx = tid + i * 256;
        int r  = idx >> 4;
        int kq = (idx & 15) << 2;
        float4 v = *reinterpret_cast<const float4*>(Q + (size_t)(m0 + r) * HD + kq);
        int sr = fa_sw(kq, r);
        Qs[(kq + 0) * 136 + sr] = f2tf(v.x);
        Qs[(kq + 1) * 136 + sr] = f2tf(v.y);
        Qs[(kq + 2) * 136 + sr] = f2tf(v.z);
        Qs[(kq + 3) * 136 + sr] = f2tf(v.w);
    }

    float acc_o[2][4][4] = {};
    float m_st[2][2] = {{-1e30f, -1e30f}, {-1e30f, -1e30f}};
    float l_st[2][2] = {};

    for (int n0 = 0; n0 < SEQ; n0 += FA_BN) {
        __syncthreads();

        #pragma unroll
        for (int i = 0; i < 4; ++i) {
            int idx = tid + i * 256;
            int n  = idx >> 4;
            int kq = (idx & 15) << 2;
            float4 v = *reinterpret_cast<const float4*>(Kg + (size_t)(n0 + n) * HD + kq);
            int sn = fa_sw(kq, n);
            Ks[(kq + 0) * 72 + sn] = f2tf(v.x);
            Ks[(kq + 1) * 72 + sn] = f2tf(v.y);
            Ks[(kq + 2) * 72 + sn] = f2tf(v.z);
            Ks[(kq + 3) * 72 + sn] = f2tf(v.w);
        }
        #pragma unroll
        for (int i = 0; i < 4; ++i) {
            int idx = tid + i * 256;
            int k  = idx >> 4;
            int dq = (idx & 15) << 2;
            float4 v = *reinterpret_cast<const float4*>(Vg + (size_t)(n0 + k) * HD + dq);
            uint32_t* dst = &Vs[k * 72 + dq];
            dst[0] = f2tf(v.x);
            dst[1] = f2tf(v.y);
            dst[2] = f2tf(v.z);
            dst[3] = f2tf(v.w);
        }
        __syncthreads();

        float acc_s[2][4][4] = {};
        #pragma unroll
        for (int ks = 0; ks < 8; ++ks) {
            uint32_t af[2][4];
            uint32_t bf[4][2];
            int k0 = ks * 8 + tg, k1 = k0 + 4;
            #pragma unroll
            for (int mt = 0; mt < 2; ++mt) {
                int r = wm + mt * 16 + g;
                af[mt][0] = Qs[k0 * 136 + fa_sw(k0, r)];
                af[mt][1] = Qs[k0 * 136 + fa_sw(k0, r + 8)];
                af[mt][2] = Qs[k1 * 136 + fa_sw(k1, r)];
                af[mt][3] = Qs[k1 * 136 + fa_sw(k1, r + 8)];
            }
            #pragma unroll
            for (int nt = 0; nt < 4; ++nt) {
                int c = wn + nt * 8 + g;
                bf[nt][0] = Ks[k0 * 72 + fa_sw(k0, c)];
                bf[nt][1] = Ks[k1 * 72 + fa_sw(k1, c)];
            }
            #pragma unroll
            for (int mt = 0; mt < 2; ++mt)
                #pragma unroll
                for (int nt = 0; nt < 4; ++nt)
                    mma8(acc_s[mt][nt], af[mt], bf[nt]);
        }
        #pragma unroll
        for (int mt = 0; mt < 2; ++mt)
            #pragma unroll
            for (int nt = 0; nt < 4; ++nt)
                #pragma unroll
                for (int e = 0; e < 4; ++e)
                    acc_s[mt][nt][e] *= 0.125f;

        #pragma unroll
        for (int mt = 0; mt < 2; ++mt)
            #pragma unroll
            for (int h = 0; h < 2; ++h) {
                float m = -1e30f;
                #pragma unroll
                for (int nt = 0; nt < 4; ++nt)
                    m = fmaxf(m, fmaxf(acc_s[mt][nt][2 * h], acc_s[mt][nt][2 * h + 1]));
                m = fmaxf(m, __shfl_xor_sync(0xffffffffu, m, 1));
                m = fmaxf(m, __shfl_xor_sync(0xffffffffu, m, 2));
                if (tg == 0) redA[nw * 128 + wm + mt * 16 + g + 8 * h] = m;
            }
        __syncthreads();

        #pragma unroll
        for (int mt = 0; mt < 2; ++mt)
            #pragma unroll
            for (int h = 0; h < 2; ++h) {
                int row = wm + mt * 16 + g + 8 * h;
                float m = fmaxf(redA[row], redA[128 + row]);
                float mnew = fmaxf(m_st[mt][h], m);
                float scale = __expf(m_st[mt][h] - mnew);
                m_st[mt][h] = mnew;
                l_st[mt][h] *= scale;
                #pragma unroll
                for (int nt = 0; nt < 4; ++nt) {
                    acc_o[mt][nt][2 * h]     *= scale;
                    acc_o[mt][nt][2 * h + 1] *= scale;
                }
                float rs = 0.f;
                #pragma unroll
                for (int nt = 0; nt < 4; ++nt) {
                    int c = wn + nt * 8 + 2 * tg;
                    float p0 = __expf(acc_s[mt][nt][2 * h]     - mnew);
                    float p1 = __expf(acc_s[mt][nt][2 * h + 1] - mnew);
                    rs += p0 + p1;
                    int rr = wm + mt * 16 + g + 8 * h;
                    Ps[c * 136 + fa_sw(c, rr)]           = f2tf(p0);
                    Ps[(c + 1) * 136 + fa_sw(c + 1, rr)] = f2tf(p1);
                }
                rs += __shfl_xor_sync(0xffffffffu, rs, 1);
                rs += __shfl_xor_sync(0xffffffffu, rs, 2);
                if (tg == 0) redB[nw * 128 + row] = rs;
            }
        __syncthreads();

        #pragma unroll
        for (int mt = 0; mt < 2; ++mt)
            #pragma unroll
            for (int h = 0; h < 2; ++h) {
                int row = wm + mt * 16 + g + 8 * h;
                l_st[mt][h] += redB[row] + redB[128 + row];
            }

        #pragma unroll
        for (int ks = 0; ks < 8; ++ks) {
            uint32_t af[2][4];
            uint32_t bf[4][2];
            int k0 = ks * 8 + tg, k1 = k0 + 4;
            #pragma unroll
            for (int mt = 0; mt < 2; ++mt) {
                int r = wm + mt * 16 + g;
                af[mt][0] = Ps[k0 * 136 + fa_sw(k0, r)];
                af[mt][1] = Ps[k0 * 136 + fa_sw(k0, r + 8)];
                af[mt][2] = Ps[k1 * 136 + fa_sw(k1, r)];
                af[mt][3] = Ps[k1 * 136 + fa_sw(k1, r + 8)];
            }
            #pragma unroll
            for (int nt = 0; nt < 4; ++nt) {
                int d = wn + nt * 8 + g;
                bf[nt][0] = Vs[k0 * 72 + d];
                bf[nt][1] = Vs[k1 * 72 + d];
            }
            #pragma unroll
            for (int mt = 0; mt < 2; ++mt)
                #pragma unroll
                for (int nt = 0; nt < 4; ++nt)
                    mma8(acc_o[mt][nt], af[mt], bf[nt]);
        }
    }

    const int b = z >> 4, h = z & 15;
    #pragma unroll
    for (int mt = 0; mt < 2; ++mt) {
        float inv0 = 1.0f / l_st[mt][0];
        float inv1 = 1.0f / l_st[mt][1];
        #pragma unroll
        for (int nt = 0; nt < 4; ++nt) {
            int s0 = m0 + wm + mt * 16 + g;
            int d0 = wn + nt * 8 + 2 * tg;
            size_t base0 = ((size_t)(b * SEQ + s0)) * EMB + h * HD;
            size_t base1 = base0 + (size_t)8 * EMB;
            g_o[base0 + d0]     = acc_o[mt][nt][0] * inv0;
            g_o[base0 + d0 + 1] = acc_o[mt][nt][1] * inv0;
            g_o[base1 + d0]     = acc_o[mt][nt][2] * inv1;
            g_o[base1 + d0 + 1] = acc_o[mt][nt][3] * inv1;
        }
    }
}

extern "C" void kernel_launch(void* const* d_in, const int* in_sizes, int n_in,
                              void* d_out, int out_size)
{
    const float* x  = (const float*)d_in[0];
    const float* Wq = (const float*)d_in[1];
    const float* bq = (const float*)d_in[2];
    const float* Wk = (const float*)d_in[3];
    const float* bk = (const float*)d_in[4];
    const float* Wv = (const float*)d_in[5];
    const float* bv = (const float*)d_in[6];
    const float* Wo = (const float*)d_in[7];
    const float* bo = (const float*)d_in[8];
    float* out = (float*)d_out;

    const int gc_smem = GC_SMEM_BYTES;       // 73728 B
    const int fa_smem = FA_SMEM_WORDS * 4;   // 108544 B
    cudaFuncSetAttribute(qkv_kernel,
                         cudaFuncAttributeMaxDynamicSharedMemorySize, gc_smem);
    cudaFuncSetAttribute(oproj_kernel,
                         cudaFuncAttributeMaxDynamicSharedMemorySize, gc_smem);
    cudaFuncSetAttribute(flash_kernel,
                         cudaFuncAttributeMaxDynamicSharedMemorySize, fa_smem);

    qkv_kernel<<<dim3(MROWS / 128, EMB / 128, 3), 256, gc_smem>>>(x, Wq, bq, Wk, bk, Wv, bv);
    flash_kernel<<<dim3(SEQ / FA_BM, 1, BH), 256, fa_smem>>>();
    oproj_kernel<<<dim3(MROWS / 128, EMB / 128, 1), 256, gc_smem>>>(Wo, bo, out);
}

// round 6
// speedup vs baseline: 2.1432x; 1.1695x over previous
#include <cuda_runtime.h>
#include <cstdint>
#include <cstddef>

#define BATCH 4
#define SEQ   1024
#define EMB   1024
#define NH    16
#define HD    64
#define BH    (BATCH * NH)      // 64
#define MROWS (BATCH * SEQ)     // 4096

// ---- scratch (device globals: allocation-free per harness rules) ----
__device__ float g_q[(size_t)BH * SEQ * HD];          // [B,H,S,D] 16 MB (tf32-rounded)
__device__ float g_k[(size_t)BH * SEQ * HD];          // 16 MB (tf32-rounded)
__device__ float g_v[(size_t)BH * SEQ * HD];          // 16 MB (tf32-rounded)
__device__ float g_o[(size_t)MROWS * EMB];            // 16 MB (tf32-rounded)
__device__ float g_x[(size_t)MROWS * EMB];            // 16 MB rounded copy of x
__device__ float g_wq[(size_t)EMB * EMB];             // 4 MB rounded Wq
__device__ float g_wk[(size_t)EMB * EMB];
__device__ float g_wv[(size_t)EMB * EMB];
__device__ float g_wo[(size_t)EMB * EMB];

// tf32 round-to-nearest; result is an fp32 bit pattern whose low mantissa
// bits are zero, so feeding it raw to mma.tf32 (which truncates) is lossless.
__device__ __forceinline__ uint32_t f2tf(float f) {
    uint32_t u;
    asm("cvt.rna.tf32.f32 %0, %1;" : "=r"(u) : "f"(f));
    return u;
}
__device__ __forceinline__ float f2tff(float f) { return __uint_as_float(f2tf(f)); }

__device__ __forceinline__ void mma8(float* c, const uint32_t* a, const uint32_t* b) {
    asm volatile(
        "mma.sync.aligned.m16n8k8.row.col.f32.tf32.tf32.f32 "
        "{%0,%1,%2,%3}, {%4,%5,%6,%7}, {%8,%9}, {%0,%1,%2,%3};\n"
        : "+f"(c[0]), "+f"(c[1]), "+f"(c[2]), "+f"(c[3])
        : "r"(a[0]), "r"(a[1]), "r"(a[2]), "r"(a[3]),
          "r"(b[0]), "r"(b[1]));
}

__device__ __forceinline__ void cp16(uint32_t dst, const void* src) {
    asm volatile("cp.async.cg.shared.global [%0], [%1], 16;\n"
                 :: "r"(dst), "l"(src));
}

// ---- kernel 0: round inputs to tf32-exact fp32 in scratch ----
__global__ void __launch_bounds__(256) preround_kernel(
    const float* __restrict__ x,
    const float* __restrict__ Wq, const float* __restrict__ Wk,
    const float* __restrict__ Wv, const float* __restrict__ Wo)
{
    const int z = blockIdx.z;
    const float* src;
    float* dst;
    size_t n;
    if (z == 0)      { src = x;  dst = g_x;  n = (size_t)MROWS * EMB; }
    else if (z == 1) { src = Wq; dst = g_wq; n = (size_t)EMB * EMB; }
    else if (z == 2) { src = Wk; dst = g_wk; n = (size_t)EMB * EMB; }
    else if (z == 3) { src = Wv; dst = g_wv; n = (size_t)EMB * EMB; }
    else             { src = Wo; dst = g_wo; n = (size_t)EMB * EMB; }

    const size_t stride = (size_t)gridDim.x * blockDim.x * 4;
    for (size_t i = ((size_t)blockIdx.x * blockDim.x + threadIdx.x) * 4;
         i < n; i += stride) {
        float4 v = *reinterpret_cast<const float4*>(src + i);
        v.x = f2tff(v.x); v.y = f2tff(v.y);
        v.z = f2tff(v.z); v.w = f2tff(v.w);
        *reinterpret_cast<float4*>(dst + i) = v;
    }
}

// ============================================================================
// double-buffered cp.async tf32 GEMM core: C[M,N] = A[M,K] * B[N,K]^T
// Operands must be tf32-rounded in gmem; fragments feed raw bits to mma.
// ============================================================================
#define GC_BM 128
#define GC_BN 128
#define GC_BK 32
#define GC_WM 64
#define GC_WN 32
#define GC_LDT (GC_BK + 4)                       // 36 words
#define GC_TILE (GC_BM * GC_LDT)
#define GC_SMEM_BYTES (2 * 2 * GC_TILE * 4)      // 73728 B

template<int MT, int NT>
__device__ __forceinline__ void gemm_core2(
    const float* __restrict__ A, int lda,
    const float* __restrict__ B, int ldb,
    int Kdim, int m0, int n0,
    float (&acc)[MT][NT][4])
{
    extern __shared__ float smem[];
    float* As = smem;                    // [2][BM][LDT]
    float* Bs = smem + 2 * GC_TILE;      // [2][BN][LDT]
    const uint32_t a_sb = (uint32_t)__cvta_generic_to_shared(As);
    const uint32_t b_sb = (uint32_t)__cvta_generic_to_shared(Bs);

    const int tid  = threadIdx.x;
    const int lane = tid & 31;
    const int warp = tid >> 5;
    const int g  = lane >> 2;
    const int tg = lane & 3;
    constexpr int WARPS_N = GC_BN / GC_WN;
    const int wm = (warp / WARPS_N) * GC_WM;
    const int wn = (warp % WARPS_N) * GC_WN;

    auto stage = [&](int buf, int k0) {
        #pragma unroll
        for (int i = 0; i < (GC_BM * GC_BK / 4) / 256; ++i) {
            int idx = tid + i * 256;
            int row = idx >> 3;
            int q   = (idx & 7) << 2;
            cp16(a_sb + (uint32_t)((buf * GC_BM + row) * GC_LDT + q) * 4,
                 A + (size_t)(m0 + row) * lda + k0 + q);
            cp16(b_sb + (uint32_t)((buf * GC_BN + row) * GC_LDT + q) * 4,
                 B + (size_t)(n0 + row) * ldb + k0 + q);
        }
    };

    stage(0, 0);
    asm volatile("cp.async.commit_group;\n");

    int s = 0;
    for (int k0 = 0; k0 < Kdim; k0 += GC_BK, s ^= 1) {
        if (k0 + GC_BK < Kdim) stage(s ^ 1, k0 + GC_BK);
        asm volatile("cp.async.commit_group;\n");
        asm volatile("cp.async.wait_group 1;\n");
        __syncthreads();

        const float* Ab = As + s * GC_TILE;
        const float* Bb = Bs + s * GC_TILE;
        #pragma unroll
        for (int ks = 0; ks < GC_BK / 8; ++ks) {
            uint32_t af[MT][4];
            uint32_t bf[NT][2];
            int kk0 = ks * 8 + tg, kk1 = kk0 + 4;
            #pragma unroll
            for (int mt = 0; mt < MT; ++mt) {
                int r = wm + mt * 16 + g;
                af[mt][0] = __float_as_uint(Ab[r * GC_LDT + kk0]);
                af[mt][1] = __float_as_uint(Ab[(r + 8) * GC_LDT + kk0]);
                af[mt][2] = __float_as_uint(Ab[r * GC_LDT + kk1]);
                af[mt][3] = __float_as_uint(Ab[(r + 8) * GC_LDT + kk1]);
            }
            #pragma unroll
            for (int nt = 0; nt < NT; ++nt) {
                int c = wn + nt * 8 + g;
                bf[nt][0] = __float_as_uint(Bb[c * GC_LDT + kk0]);
                bf[nt][1] = __float_as_uint(Bb[c * GC_LDT + kk1]);
            }
            #pragma unroll
            for (int mt = 0; mt < MT; ++mt)
                #pragma unroll
                for (int nt = 0; nt < NT; ++nt)
                    mma8(acc[mt][nt], af[mt], bf[nt]);
        }
        __syncthreads();
    }
}

// store rounded value into [B,H,S,D] with bias over flattened (h,d)
__device__ __forceinline__ void st_bhsd(float* __restrict__ out,
                                        const float* __restrict__ bias,
                                        int r, int c, float v) {
    int b = r >> 10, s = r & 1023;
    int h = c >> 6,  d = c & 63;
    out[(((size_t)b * NH + h) * SEQ + s) * HD + d] = f2tff(v + bias[c]);
}

// ---- kernel 1: fused QKV projection (grid.z selects q/k/v) ----
__global__ void __launch_bounds__(256, 2) qkv_kernel(
    const float* __restrict__ bq, const float* __restrict__ bk,
    const float* __restrict__ bv)
{
    constexpr int MT = GC_WM / 16, NT = GC_WN / 8;
    const int z = blockIdx.z;
    const float* W    = (z == 0) ? g_wq : ((z == 1) ? g_wk : g_wv);
    const float* bptr = (z == 0) ? bq   : ((z == 1) ? bk   : bv);
    float* out        = (z == 0) ? g_q  : ((z == 1) ? g_k  : g_v);

    float acc[MT][NT][4] = {};
    const int m0 = blockIdx.x * GC_BM, n0 = blockIdx.y * GC_BN;
    gemm_core2<MT, NT>(g_x, EMB, W, EMB, EMB, m0, n0, acc);

    const int lane = threadIdx.x & 31, warp = threadIdx.x >> 5;
    const int g = lane >> 2, tg = lane & 3;
    const int wm = (warp / (GC_BN / GC_WN)) * GC_WM;
    const int wn = (warp % (GC_BN / GC_WN)) * GC_WN;
    #pragma unroll
    for (int mt = 0; mt < MT; ++mt)
        #pragma unroll
        for (int nt = 0; nt < NT; ++nt) {
            int r = m0 + wm + mt * 16 + g;
            int c = n0 + wn + nt * 8 + 2 * tg;
            st_bhsd(out, bptr, r,     c,     acc[mt][nt][0]);
            st_bhsd(out, bptr, r,     c + 1, acc[mt][nt][1]);
            st_bhsd(out, bptr, r + 8, c,     acc[mt][nt][2]);
            st_bhsd(out, bptr, r + 8, c + 1, acc[mt][nt][3]);
        }
}

// ---- kernel 3: out = concat @ Wo^T + bo ----
__global__ void __launch_bounds__(256, 2) oproj_kernel(
    const float* __restrict__ bo, float* __restrict__ out)
{
    constexpr int MT = GC_WM / 16, NT = GC_WN / 8;
    float acc[MT][NT][4] = {};
    const int m0 = blockIdx.x * GC_BM, n0 = blockIdx.y * GC_BN;
    gemm_core2<MT, NT>(g_o, EMB, g_wo, EMB, EMB, m0, n0, acc);

    const int lane = threadIdx.x & 31, warp = threadIdx.x >> 5;
    const int g = lane >> 2, tg = lane & 3;
    const int wm = (warp / (GC_BN / GC_WN)) * GC_WM;
    const int wn = (warp % (GC_BN / GC_WN)) * GC_WN;
    #pragma unroll
    for (int mt = 0; mt < MT; ++mt)
        #pragma unroll
        for (int nt = 0; nt < NT; ++nt) {
            int r = m0 + wm + mt * 16 + g;
            int c = n0 + wn + nt * 8 + 2 * tg;
            out[(size_t)r * EMB + c]           = acc[mt][nt][0] + bo[c];
            out[(size_t)r * EMB + c + 1]       = acc[mt][nt][1] + bo[c + 1];
            out[(size_t)(r + 8) * EMB + c]     = acc[mt][nt][2] + bo[c];
            out[(size_t)(r + 8) * EMB + c + 1] = acc[mt][nt][3] + bo[c + 1];
        }
}

// ============================================================================
// kernel 2: fused flash attention — raw-bit tf32 on pre-rounded q/k/v,
// cp.async staging, natural layouts, conflict-free fragment strides.
// Qs [128][68], Ks [64][68], Vs [64][72], Ps [128][76]
// ============================================================================
#define FA_BM 128
#define FA_BN 64
#define FA_QLD 68
#define FA_KLD 68
#define FA_VLD 72
#define FA_PLD 76
#define FA_QS_SZ (128 * FA_QLD)
#define FA_KS_SZ (64 * FA_KLD)
#define FA_VS_SZ (64 * FA_VLD)
#define FA_PS_SZ (128 * FA_PLD)
#define FA_SMEM_WORDS (FA_QS_SZ + FA_KS_SZ + FA_VS_SZ + FA_PS_SZ + 512)

__global__ void __launch_bounds__(256, 2) flash_kernel()
{
    extern __shared__ float fsm[];
    float* Qs = fsm;
    float* Ks = Qs + FA_QS_SZ;
    float* Vs = Ks + FA_KS_SZ;
    float* Ps = Vs + FA_VS_SZ;
    float* redA = Ps + FA_PS_SZ;    // [2][128]
    float* redB = redA + 256;       // [2][128]
    const uint32_t qs_b = (uint32_t)__cvta_generic_to_shared(Qs);
    const uint32_t ks_b = (uint32_t)__cvta_generic_to_shared(Ks);
    const uint32_t vs_b = (uint32_t)__cvta_generic_to_shared(Vs);

    const int z  = blockIdx.z;
    const int m0 = blockIdx.x * FA_BM;
    const float* Q  = g_q + (size_t)z * SEQ * HD;
    const float* Kg = g_k + (size_t)z * SEQ * HD;
    const float* Vg = g_v + (size_t)z * SEQ * HD;

    const int tid  = threadIdx.x;
    const int lane = tid & 31, warp = tid >> 5;
    const int g = lane >> 2, tg = lane & 3;
    const int mw = warp >> 1, nw = warp & 1;
    const int wm = mw * 32;
    const int wn = nw * 32;

    #pragma unroll
    for (int i = 0; i < 8; ++i) {
        int idx = tid + i * 256;
        int r  = idx >> 4;
        int dq = (idx & 15) << 2;
        cp16(qs_b + (uint32_t)(r * FA_QLD + dq) * 4,
             Q + (size_t)(m0 + r) * HD + dq);
    }
    asm volatile("cp.async.commit_group;\n");

    float acc_o[2][4][4] = {};
    float m_st[2][2] = {{-1e30f, -1e30f}, {-1e30f, -1e30f}};
    float l_st[2][2] = {};

    for (int n0 = 0; n0 < SEQ; n0 += FA_BN) {
        __syncthreads();

        #pragma unroll
        for (int i = 0; i < 4; ++i) {
            int idx = tid + i * 256;
            int n  = idx >> 4;
            int dq = (idx & 15) << 2;
            cp16(ks_b + (uint32_t)(n * FA_KLD + dq) * 4,
                 Kg + (size_t)(n0 + n) * HD + dq);
            cp16(vs_b + (uint32_t)(n * FA_VLD + dq) * 4,
                 Vg + (size_t)(n0 + n) * HD + dq);
        }
        asm volatile("cp.async.commit_group;\n");
        asm volatile("cp.async.wait_group 0;\n");
        __syncthreads();

        // ---- S = Q K^T ----
        float acc_s[2][4][4] = {};
        #pragma unroll
        for (int ks = 0; ks < 8; ++ks) {
            uint32_t af[2][4];
            uint32_t bf[4][2];
            int kk0 = ks * 8 + tg, kk1 = kk0 + 4;
            #pragma unroll
            for (int mt = 0; mt < 2; ++mt) {
                int r = wm + mt * 16 + g;
                af[mt][0] = __float_as_uint(Qs[r * FA_QLD + kk0]);
                af[mt][1] = __float_as_uint(Qs[(r + 8) * FA_QLD + kk0]);
                af[mt][2] = __float_as_uint(Qs[r * FA_QLD + kk1]);
                af[mt][3] = __float_as_uint(Qs[(r + 8) * FA_QLD + kk1]);
            }
            #pragma unroll
            for (int nt = 0; nt < 4; ++nt) {
                int c = wn + nt * 8 + g;
                bf[nt][0] = __float_as_uint(Ks[c * FA_KLD + kk0]);
                bf[nt][1] = __float_as_uint(Ks[c * FA_KLD + kk1]);
            }
            #pragma unroll
            for (int mt = 0; mt < 2; ++mt)
                #pragma unroll
                for (int nt = 0; nt < 4; ++nt)
                    mma8(acc_s[mt][nt], af[mt], bf[nt]);
        }
        #pragma unroll
        for (int mt = 0; mt < 2; ++mt)
            #pragma unroll
            for (int nt = 0; nt < 4; ++nt)
                #pragma unroll
                for (int e = 0; e < 4; ++e)
                    acc_s[mt][nt][e] *= 0.125f;

        // ---- row max ----
        #pragma unroll
        for (int mt = 0; mt < 2; ++mt)
            #pragma unroll
            for (int h = 0; h < 2; ++h) {
                float m = -1e30f;
                #pragma unroll
                for (int nt = 0; nt < 4; ++nt)
                    m = fmaxf(m, fmaxf(acc_s[mt][nt][2 * h], acc_s[mt][nt][2 * h + 1]));
                m = fmaxf(m, __shfl_xor_sync(0xffffffffu, m, 1));
                m = fmaxf(m, __shfl_xor_sync(0xffffffffu, m, 2));
                if (tg == 0) redA[nw * 128 + wm + mt * 16 + g + 8 * h] = m;
            }
        __syncthreads();

        // ---- online softmax + write rounded P ----
        #pragma unroll
        for (int mt = 0; mt < 2; ++mt)
            #pragma unroll
            for (int h = 0; h < 2; ++h) {
                int row = wm + mt * 16 + g + 8 * h;
                float m = fmaxf(redA[row], redA[128 + row]);
                float mnew = fmaxf(m_st[mt][h], m);
                float scale = __expf(m_st[mt][h] - mnew);
                m_st[mt][h] = mnew;
                l_st[mt][h] *= scale;
                #pragma unroll
                for (int nt = 0; nt < 4; ++nt) {
                    acc_o[mt][nt][2 * h]     *= scale;
                    acc_o[mt][nt][2 * h + 1] *= scale;
                }
                float rs = 0.f;
                #pragma unroll
                for (int nt = 0; nt < 4; ++nt) {
                    int c = wn + nt * 8 + 2 * tg;
                    float p0 = __expf(acc_s[mt][nt][2 * h]     - mnew);
                    float p1 = __expf(acc_s[mt][nt][2 * h + 1] - mnew);
                    rs += p0 + p1;
                    Ps[row * FA_PLD + c]     = f2tff(p0);
                    Ps[row * FA_PLD + c + 1] = f2tff(p1);
                }
                rs += __shfl_xor_sync(0xffffffffu, rs, 1);
                rs += __shfl_xor_sync(0xffffffffu, rs, 2);
                if (tg == 0) redB[nw * 128 + row] = rs;
            }
        __syncthreads();

        #pragma unroll
        for (int mt = 0; mt < 2; ++mt)
            #pragma unroll
            for (int h = 0; h < 2; ++h) {
                int row = wm + mt * 16 + g + 8 * h;
                l_st[mt][h] += redB[row] + redB[128 + row];
            }

        // ---- O += P V ----
        #pragma unroll
        for (int ks = 0; ks < 8; ++ks) {
            uint32_t af[2][4];
            uint32_t bf[4][2];
            int kk0 = ks * 8 + tg, kk1 = kk0 + 4;
            #pragma unroll
            for (int mt = 0; mt < 2; ++mt) {
                int r = wm + mt * 16 + g;
                af[mt][0] = __float_as_uint(Ps[r * FA_PLD + kk0]);
                af[mt][1] = __float_as_uint(Ps[(r + 8) * FA_PLD + kk0]);
                af[mt][2] = __float_as_uint(Ps[r * FA_PLD + kk1]);
                af[mt][3] = __float_as_uint(Ps[(r + 8) * FA_PLD + kk1]);
            }
            #pragma unroll
            for (int nt = 0; nt < 4; ++nt) {
                int d = wn + nt * 8 + g;
                bf[nt][0] = __float_as_uint(Vs[kk0 * FA_VLD + d]);
                bf[nt][1] = __float_as_uint(Vs[kk1 * FA_VLD + d]);
            }
            #pragma unroll
            for (int mt = 0; mt < 2; ++mt)
                #pragma unroll
                for (int nt = 0; nt < 4; ++nt)
                    mma8(acc_o[mt][nt], af[mt], bf[nt]);
        }
    }

    // ---- epilogue: O /= l, rounded for oproj, concat layout [B,S,H*D] ----
    const int b = z >> 4, h = z & 15;
    #pragma unroll
    for (int mt = 0; mt < 2; ++mt) {
        float inv0 = 1.0f / l_st[mt][0];
        float inv1 = 1.0f / l_st[mt][1];
        #pragma unroll
        for (int nt = 0; nt < 4; ++nt) {
            int s0 = m0 + wm + mt * 16 + g;
            int d0 = wn + nt * 8 + 2 * tg;
            size_t base0 = ((size_t)(b * SEQ + s0)) * EMB + h * HD;
            size_t base1 = base0 + (size_t)8 * EMB;
            g_o[base0 + d0]     = f2tff(acc_o[mt][nt][0] * inv0);
            g_o[base0 + d0 + 1] = f2tff(acc_o[mt][nt][1] * inv0);
            g_o[base1 + d0]     = f2tff(acc_o[mt][nt][2] * inv1);
            g_o[base1 + d0 + 1] = f2tff(acc_o[mt][nt][3] * inv1);
        }
    }
}

extern "C" void kernel_launch(void* const* d_in, const int* in_sizes, int n_in,
                              void* d_out, int out_size)
{
    const float* x  = (const float*)d_in[0];
    const float* Wq = (const float*)d_in[1];
    const float* bq = (const float*)d_in[2];
    const float* Wk = (const float*)d_in[3];
    const float* bk = (const float*)d_in[4];
    const float* Wv = (const float*)d_in[5];
    const float* bv = (const float*)d_in[6];
    const float* Wo = (const float*)d_in[7];
    const float* bo = (const float*)d_in[8];
    float* out = (float*)d_out;

    const int gc_smem = GC_SMEM_BYTES;       // 73728 B
    const int fa_smem = FA_SMEM_WORDS * 4;   // 111616 B
    cudaFuncSetAttribute(qkv_kernel,
                         cudaFuncAttributeMaxDynamicSharedMemorySize, gc_smem);
    cudaFuncSetAttribute(oproj_kernel,
                         cudaFuncAttributeMaxDynamicSharedMemorySize, gc_smem);
    cudaFuncSetAttribute(flash_kernel,
                         cudaFuncAttributeMaxDynamicSharedMemorySize, fa_smem);

    preround_kernel<<<dim3(1024, 1, 5), 256>>>(x, Wq, Wk, Wv, Wo);
    qkv_kernel<<<dim3(MROWS / 128, EMB / 128, 3), 256, gc_smem>>>(bq, bk, bv);
    flash_kernel<<<dim3(SEQ / FA_BM, 1, BH), 256, fa_smem>>>();
    oproj_kernel<<<dim3(MROWS / 128, EMB / 128, 1), 256, gc_smem>>>(bo, out);
}